// round 6
// baseline (speedup 1.0000x reference)
#include <cuda_runtime.h>
#include <cuda_bf16.h>
#include <cstdint>

#define N_ROIS   32768
#define N_GT     1024
#define N_IMAGES 8
#define NTHREADS 512
#define ROIS_PER_BLOCK 128
#define NBLOCKS  (N_ROIS / ROIS_PER_BLOCK)   // 256

// ---------------------------------------------------------------------------
// Single fused kernel, 4 threads per ROI:
//   Phase 1: per-block stable GT bucketing (batch-compacted) into shared mem
//   Phase 2: block-local ROI sort by batch (128 ROIs, ballot-based)
//   Phase 3: per-ROI argmax IoU; GT range split across 4 threads (quarters),
//            each with 4 independent division-free chains; shfl_xor merge.
// ---------------------------------------------------------------------------
#define IOU_STEP(J, BI, BU, BJ) {                               \
    float4 g  = sbox[J];                                        \
    float ag  = sarea[J];                                       \
    float iw  = fminf(rx2p, g.z) - fmaxf(rx1, g.x);             \
    float ih  = fminf(ry2p, g.w) - fmaxf(ry1, g.y);             \
    float inter = fmaxf(iw, 0.0f) * ih;                         \
    float uni   = (area_r + ag) - inter;                        \
    bool better = inter * (BU) > (BI) * uni;                    \
    BI = better ? inter : (BI);                                 \
    BU = better ? uni   : (BU);                                 \
    BJ = better ? (J)   : (BJ);                                 \
}

// merge (bi,bu,bj) <- other if other's iou greater, or equal with smaller j
#define MERGE(OBI, OBU, OBJ) {                                  \
    float a = (OBI) * bu, c = bi * (OBU);                       \
    bool take = (a > c) ||                                      \
        (a == c && (unsigned)(OBJ) < (unsigned)bj);             \
    bi = take ? (OBI) : bi;                                     \
    bu = take ? (OBU) : bu;                                     \
    bj = take ? (OBJ) : bj;                                     \
}

__global__ void __launch_bounds__(NTHREADS) roitarget_fused(const float* __restrict__ rois,
                                                            const int* __restrict__ rb,
                                                            const float* __restrict__ gt,
                                                            const int* __restrict__ gb,
                                                            float* __restrict__ out) {
    __shared__ float4 sbox[N_GT];            // 16KB: x1, y1, x2+1, y2+1 (batch-compacted)
    __shared__ float  sarea[N_GT];           // 4KB
    __shared__ float  slab[N_GT];            // 4KB
    __shared__ int    sgb[N_GT];             // 4KB staged gt batch ids
    __shared__ int    sgcnt[N_IMAGES];
    __shared__ int    sgoff[N_IMAGES + 1];
    __shared__ int    swc[4][8];             // per-warp per-batch ROI counts (phase 2)
    __shared__ int    wbase[4][8];
    __shared__ int    ssrc[ROIS_PER_BLOCK];  // sorted pos -> original ROI index
    __shared__ int    ssb[ROIS_PER_BLOCK];   // sorted pos -> batch

    const int tid  = threadIdx.x;
    const int w    = tid >> 5;
    const int lane = tid & 31;
    const unsigned lt = (1u << lane) - 1u;

    // ---------------- Phase 1: GT bucketing (stable within batch) ----------
    for (int j = tid; j < N_GT; j += NTHREADS) sgb[j] = gb[j];
    __syncthreads();

    if (w < 8) {   // warp w owns batch w
        int cnt = 0;
        for (int j0 = 0; j0 < N_GT; j0 += 32) {
            int bb = sgb[j0 + lane];
            unsigned m = __ballot_sync(0xffffffffu, bb == w);
            cnt += __popc(m);
        }
        if (lane == 0) sgcnt[w] = cnt;
    }
    __syncthreads();
    if (tid == 0) {
        int o = 0;
        for (int b = 0; b < N_IMAGES; b++) { sgoff[b] = o; o += sgcnt[b]; }
        sgoff[N_IMAGES] = o;
    }
    __syncthreads();

    if (w < 8) {
        int pos = sgoff[w];
        for (int j0 = 0; j0 < N_GT; j0 += 32) {
            int j = j0 + lane;
            int bb = sgb[j];
            bool mine = (bb == w);
            unsigned m = __ballot_sync(0xffffffffu, mine);
            if (mine) {
                int idx = pos + __popc(m & lt);
                const float* p = gt + 5 * j;
                float x1 = p[0], y1 = p[1], x2 = p[2], y2 = p[3], cls = p[4];
                sbox[idx]  = make_float4(x1, y1, x2 + 1.0f, y2 + 1.0f);
                sarea[idx] = ((x2 - x1) + 1.0f) * ((y2 - y1) + 1.0f);
                slab[idx]  = cls;
            }
            pos += __popc(m);
        }
    }

    // ---------------- Phase 2: block-local ROI sort by batch (128 ROIs) ----
    if (tid < ROIS_PER_BLOCK) {
        const int i = blockIdx.x * ROIS_PER_BLOCK + tid;
        const int myb = rb[i];
        int myrank = 0;
#pragma unroll
        for (int bb = 0; bb < N_IMAGES; bb++) {
            unsigned m = __ballot_sync(0xffffffffu, myb == bb);
            if (myb == bb) myrank = __popc(m & lt);
            if (lane == 0) swc[w][bb] = __popc(m);
        }
        __syncwarp();
        // stash rank in ssb temporarily? No: recompute dest after bases ready.
        // Save myb/myrank in registers; need bases first.
        // (fall through; dest computed after syncthreads below)
        // To keep it simple, store (myb, myrank, i) via registers and a second if-block.
        ssb[tid] = myb;        // provisional; overwritten below
        ssrc[tid] = myrank;    // provisional
    }
    __syncthreads();
    if (tid < 32) {
        int ww = tid >> 3, bb = tid & 7;
        int o = 0;
        for (int b2 = 0; b2 < bb; b2++)
#pragma unroll
            for (int w2 = 0; w2 < 4; w2++) o += swc[w2][b2];
        for (int w2 = 0; w2 < ww; w2++) o += swc[w2][bb];
        wbase[ww][bb] = o;
    }
    __syncthreads();
    // scatter: read provisional (myb, myrank) then overwrite sorted arrays
    int sc_dest = -1, sc_i = 0, sc_b = 0;
    if (tid < ROIS_PER_BLOCK) {
        sc_b = ssb[tid];
        int rank = ssrc[tid];
        sc_dest = wbase[w][sc_b] + rank;
        sc_i = blockIdx.x * ROIS_PER_BLOCK + tid;
    }
    __syncthreads();
    if (sc_dest >= 0) {
        ssrc[sc_dest] = sc_i;
        ssb[sc_dest]  = sc_b;
    }
    __syncthreads();

    // ---------------- Phase 3: 4 threads per ROI ---------------------------
    const int s = tid >> 2;          // ROI slot 0..127
    const int q = tid & 3;           // quarter
    const int ii = ssrc[s];
    const int b  = ssb[s];

    const float* r = rois + 5 * ii;
    const float rx1 = __ldg(r + 0), ry1 = __ldg(r + 1);
    const float rx2 = __ldg(r + 2), ry2 = __ldg(r + 3);
    const float rx2p = rx2 + 1.0f;
    const float ry2p = ry2 + 1.0f;
    const float ew = (rx2 - rx1) + 1.0f;
    const float eh = (ry2 - ry1) + 1.0f;
    const float area_r = ew * eh;

    const int j0 = sgoff[b];
    const int j1 = sgoff[b + 1];
    const int len  = j1 - j0;
    const int qlen = (len + 3) >> 2;
    const int js = j0 + q * qlen;
    const int je = min(js + qlen, j1);

    float bi0 = 0.0f, bu0 = 1.0f; int bj0 = -1;
    float bi1 = 0.0f, bu1 = 1.0f; int bj1 = -1;
    float bi2 = 0.0f, bu2 = 1.0f; int bj2 = -1;
    float bi3 = 0.0f, bu3 = 1.0f; int bj3 = -1;

    int j = js;
    for (; j + 4 <= je; j += 4) {
        IOU_STEP(j + 0, bi0, bu0, bj0);
        IOU_STEP(j + 1, bi1, bu1, bj1);
        IOU_STEP(j + 2, bi2, bu2, bj2);
        IOU_STEP(j + 3, bi3, bu3, bj3);
    }
    for (; j < je; ++j) {
        IOU_STEP(j, bi0, bu0, bj0);
    }

    // in-thread chain merge (ascending j order preserved by tie-break)
    float bi = bi0, bu = bu0; int bj = bj0;
    MERGE(bi1, bu1, bj1);
    MERGE(bi2, bu2, bj2);
    MERGE(bi3, bu3, bj3);

    // cross-quarter butterfly merge (lanes q^1, q^2)
#pragma unroll
    for (int d = 1; d <= 2; d <<= 1) {
        float obi = __shfl_xor_sync(0xffffffffu, bi, d);
        float obu = __shfl_xor_sync(0xffffffffu, bu, d);
        int   obj = __shfl_xor_sync(0xffffffffu, bj, d);
        MERGE(obi, obu, obj);
    }

    if (q == 0) {
        const float iou = bi / bu;
        const bool  fg  = (bj >= 0) && (iou >= 0.5f);

        float lbl = 0.0f, dx = 0.0f, dy = 0.0f, dw = 0.0f, dh = 0.0f, wgt = 0.0f;
        if (fg) {
            float4 g = sbox[bj];
            float gw  = g.z - g.x;               // (x2+1) - x1
            float gh  = g.w - g.y;
            float gcx = g.x + 0.5f * gw;
            float gcy = g.y + 0.5f * gh;
            float ecx = rx1 + 0.5f * ew;
            float ecy = ry1 + 0.5f * eh;
            dx = (gcx - ecx) / ew;
            dy = (gcy - ecy) / eh;
            dw = logf(gw / ew);
            dh = logf(gh / eh);
            lbl = slab[bj];
            wgt = 1.0f;
        }

        // Layout: labels[N] | deltas[N][4] | bbwgts[N][1]
        out[ii] = lbl;
        reinterpret_cast<float4*>(out + N_ROIS)[ii] = make_float4(dx, dy, dw, dh);
        out[N_ROIS * 5 + ii] = wgt;
    }
}

extern "C" void kernel_launch(void* const* d_in, const int* in_sizes, int n_in,
                              void* d_out, int out_size) {
    const float* rois = (const float*)d_in[0];
    const int*   rb   = (const int*)d_in[1];
    const float* gt   = (const float*)d_in[2];
    const int*   gb   = (const int*)d_in[3];
    float* out = (float*)d_out;

    roitarget_fused<<<NBLOCKS, NTHREADS>>>(rois, rb, gt, gb, out);
}

// round 7
// speedup vs baseline: 1.6441x; 1.6441x over previous
#include <cuda_runtime.h>
#include <cuda_bf16.h>
#include <cstdint>

#define N_ROIS   32768
#define N_GT     1024
#define N_IMAGES 8
#define NTHREADS 512
#define ROIS_PER_BLOCK 128
#define NBLOCKS  (N_ROIS / ROIS_PER_BLOCK)   // 256

// ---------------------------------------------------------------------------
// One fused kernel:
//  Phase 1: parallel-rank GT bucketing (2 GTs/thread, ballot counts per
//           32-element chunk, shfl-scan over 32 chunks, direct scatter).
//  Phase 2: block-local ROI sort by batch (128 ROIs, ballot-based).
//  Phase 3: 4 threads/ROI, interleaved quarters (j0+16t+4k+q) -> each warp
//           step reads one contiguous 64B smem segment; 4 chains; shfl merge.
// ---------------------------------------------------------------------------
#define IOU_STEP(J, BI, BU, BJ) {                               \
    float4 g  = sbox[J];                                        \
    float ag  = sarea[J];                                       \
    float iw  = fminf(rx2p, g.z) - fmaxf(rx1, g.x);             \
    float ih  = fminf(ry2p, g.w) - fmaxf(ry1, g.y);             \
    float inter = fmaxf(iw, 0.0f) * ih;                         \
    float uni   = (area_r + ag) - inter;                        \
    bool better = inter * (BU) > (BI) * uni;                    \
    BI = better ? inter : (BI);                                 \
    BU = better ? uni   : (BU);                                 \
    BJ = better ? (J)   : (BJ);                                 \
}

#define MERGE(OBI, OBU, OBJ) {                                  \
    float a = (OBI) * bu, c = bi * (OBU);                       \
    bool take = (a > c) ||                                      \
        (a == c && (unsigned)(OBJ) < (unsigned)bj);             \
    bi = take ? (OBI) : bi;                                     \
    bu = take ? (OBU) : bu;                                     \
    bj = take ? (OBJ) : bj;                                     \
}

__global__ void __launch_bounds__(NTHREADS) roitarget_fused(const float* __restrict__ rois,
                                                            const int* __restrict__ rb,
                                                            const float* __restrict__ gt,
                                                            const int* __restrict__ gb,
                                                            float* __restrict__ out) {
    __shared__ float4 sbox[N_GT];            // 16KB compacted: x1,y1,x2+1,y2+1
    __shared__ float  sarea[N_GT];           // 4KB
    __shared__ float  slab[N_GT];            // 4KB
    __shared__ int    sgcnt[32][8];          // per-chunk per-batch GT counts
    __shared__ int    sexcl[32][8];          // exclusive chunk prefix per batch
    __shared__ int    stot[N_IMAGES];
    __shared__ int    soff[N_IMAGES + 1];    // GT batch offsets
    __shared__ int    swc[4][8];             // phase-2 per-warp per-batch counts
    __shared__ int    wbase[4][8];
    __shared__ int    ssrc[ROIS_PER_BLOCK];  // sorted pos -> original ROI index
    __shared__ int    ssb[ROIS_PER_BLOCK];   // sorted pos -> batch

    const int tid  = threadIdx.x;
    const int w    = tid >> 5;
    const int lane = tid & 31;
    const unsigned lt = (1u << lane) - 1u;

    // ---------------- Phase 1: parallel GT bucketing -----------------------
    const int ja = tid;            // chunk w      (j in [32w, 32w+32))
    const int jb = tid + 512;      // chunk 16+w
    const int ba = gb[ja];
    const int bb = gb[jb];
    int ranka = 0, rankb = 0;
#pragma unroll
    for (int b = 0; b < N_IMAGES; b++) {
        unsigned ma = __ballot_sync(0xffffffffu, ba == b);
        if (ba == b) ranka = __popc(ma & lt);
        if (lane == 0) sgcnt[w][b] = __popc(ma);
        unsigned mb = __ballot_sync(0xffffffffu, bb == b);
        if (bb == b) rankb = __popc(mb & lt);
        if (lane == 0) sgcnt[16 + w][b] = __popc(mb);
    }
    __syncthreads();

    // per-batch exclusive scan over 32 chunks: warp b handles batch b, lane=chunk
    if (w < N_IMAGES) {
        int v = sgcnt[lane][w];
        int incl = v;
#pragma unroll
        for (int d = 1; d < 32; d <<= 1) {
            int t = __shfl_up_sync(0xffffffffu, incl, d);
            if (lane >= d) incl += t;
        }
        sexcl[lane][w] = incl - v;
        if (lane == 31) stot[w] = incl;
    }
    __syncthreads();
    if (tid == 0) {
        int o = 0;
        for (int b = 0; b < N_IMAGES; b++) { soff[b] = o; o += stot[b]; }
        soff[N_IMAGES] = o;
    }
    __syncthreads();

    // scatter both GTs to compacted slots
    {
        const int da = soff[ba] + sexcl[w][ba] + ranka;
        const float* p = gt + 5 * ja;
        float x1 = p[0], y1 = p[1], x2 = p[2], y2 = p[3], cls = p[4];
        sbox[da]  = make_float4(x1, y1, x2 + 1.0f, y2 + 1.0f);
        sarea[da] = ((x2 - x1) + 1.0f) * ((y2 - y1) + 1.0f);
        slab[da]  = cls;

        const int db = soff[bb] + sexcl[16 + w][bb] + rankb;
        const float* p2 = gt + 5 * jb;
        float u1 = p2[0], v1 = p2[1], u2 = p2[2], v2 = p2[3], cl2 = p2[4];
        sbox[db]  = make_float4(u1, v1, u2 + 1.0f, v2 + 1.0f);
        sarea[db] = ((u2 - u1) + 1.0f) * ((v2 - v1) + 1.0f);
        slab[db]  = cl2;
    }

    // ---------------- Phase 2: block-local ROI sort by batch ---------------
    if (tid < ROIS_PER_BLOCK) {
        const int i = blockIdx.x * ROIS_PER_BLOCK + tid;
        const int myb = rb[i];
        int myrank = 0;
#pragma unroll
        for (int b2 = 0; b2 < N_IMAGES; b2++) {
            unsigned m = __ballot_sync(0xffffffffu, myb == b2);
            if (myb == b2) myrank = __popc(m & lt);
            if (lane == 0) swc[w][b2] = __popc(m);
        }
        __syncwarp();
        ssb[tid]  = myb;       // provisional
        ssrc[tid] = myrank;    // provisional
    }
    __syncthreads();
    if (tid < 32) {
        int ww = tid >> 3, b2 = tid & 7;
        int o = 0;
        for (int b3 = 0; b3 < b2; b3++)
#pragma unroll
            for (int w2 = 0; w2 < 4; w2++) o += swc[w2][b3];
        for (int w2 = 0; w2 < ww; w2++) o += swc[w2][b2];
        wbase[ww][b2] = o;
    }
    __syncthreads();
    int sc_dest = -1, sc_i = 0, sc_b = 0;
    if (tid < ROIS_PER_BLOCK) {
        sc_b = ssb[tid];
        int rank = ssrc[tid];
        sc_dest = wbase[w][sc_b] + rank;
        sc_i = blockIdx.x * ROIS_PER_BLOCK + tid;
    }
    __syncthreads();
    if (sc_dest >= 0) {
        ssrc[sc_dest] = sc_i;
        ssb[sc_dest]  = sc_b;
    }
    __syncthreads();

    // ---------------- Phase 3: 4 threads per ROI, interleaved quarters -----
    const int s = tid >> 2;          // ROI slot 0..127
    const int q = tid & 3;           // quarter
    const int ii = ssrc[s];
    const int b  = ssb[s];

    const float* r = rois + 5 * ii;
    const float rx1 = __ldg(r + 0), ry1 = __ldg(r + 1);
    const float rx2 = __ldg(r + 2), ry2 = __ldg(r + 3);
    const float rx2p = rx2 + 1.0f;
    const float ry2p = ry2 + 1.0f;
    const float ew = (rx2 - rx1) + 1.0f;
    const float eh = (ry2 - ry1) + 1.0f;
    const float area_r = ew * eh;

    const int j0 = soff[b];
    const int j1 = soff[b + 1];
    const int len = j1 - j0;
    const int nfull = len >> 4;      // groups of 16

    float bi0 = 0.0f, bu0 = 1.0f; int bj0 = -1;
    float bi1 = 0.0f, bu1 = 1.0f; int bj1 = -1;
    float bi2 = 0.0f, bu2 = 1.0f; int bj2 = -1;
    float bi3 = 0.0f, bu3 = 1.0f; int bj3 = -1;

    int base = j0 + q;
    for (int t = 0; t < nfull; t++, base += 16) {
        IOU_STEP(base + 0,  bi0, bu0, bj0);
        IOU_STEP(base + 4,  bi1, bu1, bj1);
        IOU_STEP(base + 8,  bi2, bu2, bj2);
        IOU_STEP(base + 12, bi3, bu3, bj3);
    }
    // tail (len % 16 elements), stride 4 per quarter, chain 0
    for (int j = j0 + (nfull << 4) + q; j < j1; j += 4) {
        IOU_STEP(j, bi0, bu0, bj0);
    }

    // in-thread chain merge (ties -> smaller j)
    float bi = bi0, bu = bu0; int bj = bj0;
    MERGE(bi1, bu1, bj1);
    MERGE(bi2, bu2, bj2);
    MERGE(bi3, bu3, bj3);

    // cross-quarter butterfly merge
#pragma unroll
    for (int d = 1; d <= 2; d <<= 1) {
        float obi = __shfl_xor_sync(0xffffffffu, bi, d);
        float obu = __shfl_xor_sync(0xffffffffu, bu, d);
        int   obj = __shfl_xor_sync(0xffffffffu, bj, d);
        MERGE(obi, obu, obj);
    }

    if (q == 0) {
        const float iou = bi / bu;
        const bool  fg  = (bj >= 0) && (iou >= 0.5f);

        float lbl = 0.0f, dx = 0.0f, dy = 0.0f, dw = 0.0f, dh = 0.0f, wgt = 0.0f;
        if (fg) {
            float4 g = sbox[bj];
            float gw  = g.z - g.x;               // (x2+1) - x1
            float gh  = g.w - g.y;
            float gcx = g.x + 0.5f * gw;
            float gcy = g.y + 0.5f * gh;
            float ecx = rx1 + 0.5f * ew;
            float ecy = ry1 + 0.5f * eh;
            dx = (gcx - ecx) / ew;
            dy = (gcy - ecy) / eh;
            dw = logf(gw / ew);
            dh = logf(gh / eh);
            lbl = slab[bj];
            wgt = 1.0f;
        }

        // Layout: labels[N] | deltas[N][4] | bbwgts[N][1]
        out[ii] = lbl;
        reinterpret_cast<float4*>(out + N_ROIS)[ii] = make_float4(dx, dy, dw, dh);
        out[N_ROIS * 5 + ii] = wgt;
    }
}

extern "C" void kernel_launch(void* const* d_in, const int* in_sizes, int n_in,
                              void* d_out, int out_size) {
    const float* rois = (const float*)d_in[0];
    const int*   rb   = (const int*)d_in[1];
    const float* gt   = (const float*)d_in[2];
    const int*   gb   = (const int*)d_in[3];
    float* out = (float*)d_out;

    roitarget_fused<<<NBLOCKS, NTHREADS>>>(rois, rb, gt, gb, out);
}